// round 1
// baseline (speedup 1.0000x reference)
#include <cuda_runtime.h>
#include <math_constants.h>
#include <cstdint>
#include <cstddef>

// ---------------------------------------------------------------------------
// KNN classifier (cosine similarity, top-k=20 vote over 9 classes)
//   train_features: [100000, 256] f32   (d_in[0])
//   train_labels  : [100000]      i32   (d_in[1])
//   x             : [2048, 256]   f32   (d_in[2])
//   k             : scalar int          (d_in[3], if present)
//   out           : [2048]        f32   (predicted class)
//
// Ordering trick: sim[i,j] = <x_i,t_j> / (||x_i||*||t_j||); ||x_i|| is
// constant per output row, so top-k ordering only needs <x_i,t_j>/||t_j||.
// ---------------------------------------------------------------------------

#define NCLASS 9
#define MAXK   32

// Scratch (device-global arrays: the allowed no-alloc workaround).
// 2048 * 100000 f32 = 819.2 MB similarity matrix.
static __device__ __align__(16) float g_sims[(size_t)2048 * 100000];
static __device__ float g_invnorm[100096];

// ---------------------------------------------------------------------------
// Phase 0: inverse L2 norm of each training row. Warp per row, float4 loads.
// ---------------------------------------------------------------------------
__global__ void norm_kernel(const float* __restrict__ T, int n, int d)
{
    int gw   = (int)((blockIdx.x * blockDim.x + threadIdx.x) >> 5);
    int lane = threadIdx.x & 31;
    if (gw >= n) return;
    const float* row = T + (size_t)gw * d;
    float s = 0.f;
    for (int i = lane * 4; i < d; i += 128) {
        float4 v = *(const float4*)(row + i);
        s += v.x * v.x + v.y * v.y + v.z * v.z + v.w * v.w;
    }
    #pragma unroll
    for (int o = 16; o > 0; o >>= 1)
        s += __shfl_xor_sync(0xffffffffu, s, o);
    if (lane == 0)
        g_invnorm[gw] = rsqrtf(fmaxf(s, 1e-30f));
}

// ---------------------------------------------------------------------------
// Phase 1: sims[m][n] = dot(x[m], train[n]) * invnorm[n]
// Tiled fp32 SGEMM, 128x128 block tile, BK=16, 256 threads, 8x8 per-thread
// register micro-tile, float4 shared loads, register-prefetch of next k-tile.
// Both operands are K-contiguous row-major ("NT" gemm) -> tiles stored
// K-transposed in shared for vectorized reads.
// ---------------------------------------------------------------------------
__global__ __launch_bounds__(256, 2)
void gemm_sim_kernel(const float* __restrict__ A,   // x      [M, K]
                     const float* __restrict__ B,   // train  [N, K]
                     int M, int N, int K)
{
    __shared__ __align__(16) float As[16][132];
    __shared__ __align__(16) float Bs[16][132];
    __shared__ float sInv[128];

    const int tid = threadIdx.x;
    const int m0  = blockIdx.x * 128;
    const int n0  = blockIdx.y * 128;

    if (tid < 128) {
        int n = n0 + tid;
        sInv[tid] = (n < N) ? g_invnorm[n] : 0.0f;
    }

    const int tn = (tid & 15) << 2;   // 0,4,...,60
    const int tm = (tid >> 4) << 2;   // 0,4,...,60

    // Global-load mapping: thread -> row tid/2, two float4 quads of its K-slice
    const int ldRow = tid >> 1;              // 0..127
    const int ldQ   = (tid & 1) * 2;         // quad base: 0 or 2
    const bool aValid = (m0 + ldRow) < M;
    const bool bValid = (n0 + ldRow) < N;
    const float* Aptr = A + (size_t)(m0 + ldRow) * K;
    const float* Bptr = B + (size_t)(n0 + ldRow) * K;

    float4 pa[2], pb[2];
    float acc[8][8];
    #pragma unroll
    for (int i = 0; i < 8; i++)
        #pragma unroll
        for (int j = 0; j < 8; j++) acc[i][j] = 0.f;

    const int nkt = K >> 4;   // K assumed multiple of 16 (K=256)

    // initial tile load
    #pragma unroll
    for (int it = 0; it < 2; it++) {
        int q = ldQ + it;
        pa[it] = aValid ? *(const float4*)(Aptr + q * 4) : make_float4(0, 0, 0, 0);
        pb[it] = bValid ? *(const float4*)(Bptr + q * 4) : make_float4(0, 0, 0, 0);
    }
    #pragma unroll
    for (int it = 0; it < 2; it++) {
        int q = ldQ + it;
        As[q * 4 + 0][ldRow] = pa[it].x;  As[q * 4 + 1][ldRow] = pa[it].y;
        As[q * 4 + 2][ldRow] = pa[it].z;  As[q * 4 + 3][ldRow] = pa[it].w;
        Bs[q * 4 + 0][ldRow] = pb[it].x;  Bs[q * 4 + 1][ldRow] = pb[it].y;
        Bs[q * 4 + 2][ldRow] = pb[it].z;  Bs[q * 4 + 3][ldRow] = pb[it].w;
    }
    __syncthreads();

    for (int kt = 1; kt <= nkt; kt++) {
        if (kt < nkt) {
            int k0 = kt << 4;
            #pragma unroll
            for (int it = 0; it < 2; it++) {
                int q = ldQ + it;
                pa[it] = aValid ? *(const float4*)(Aptr + k0 + q * 4) : make_float4(0, 0, 0, 0);
                pb[it] = bValid ? *(const float4*)(Bptr + k0 + q * 4) : make_float4(0, 0, 0, 0);
            }
        }
        #pragma unroll
        for (int k = 0; k < 16; k++) {
            float a[8], b[8];
            *(float4*)&a[0] = *(const float4*)&As[k][tm];
            *(float4*)&a[4] = *(const float4*)&As[k][64 + tm];
            *(float4*)&b[0] = *(const float4*)&Bs[k][tn];
            *(float4*)&b[4] = *(const float4*)&Bs[k][64 + tn];
            #pragma unroll
            for (int i = 0; i < 8; i++)
                #pragma unroll
                for (int j = 0; j < 8; j++)
                    acc[i][j] = fmaf(a[i], b[j], acc[i][j]);
        }
        __syncthreads();
        if (kt < nkt) {
            #pragma unroll
            for (int it = 0; it < 2; it++) {
                int q = ldQ + it;
                As[q * 4 + 0][ldRow] = pa[it].x;  As[q * 4 + 1][ldRow] = pa[it].y;
                As[q * 4 + 2][ldRow] = pa[it].z;  As[q * 4 + 3][ldRow] = pa[it].w;
                Bs[q * 4 + 0][ldRow] = pb[it].x;  Bs[q * 4 + 1][ldRow] = pb[it].y;
                Bs[q * 4 + 2][ldRow] = pb[it].z;  Bs[q * 4 + 3][ldRow] = pb[it].w;
            }
            __syncthreads();
        }
    }

    // Epilogue: scale by inv-norm, guarded float4 stores into g_sims.
    #pragma unroll
    for (int i = 0; i < 8; i++) {
        int mi = m0 + ((i < 4) ? (tm + i) : (64 + tm + i - 4));
        if (mi >= M) continue;
        float* Crow = g_sims + (size_t)mi * N;
        #pragma unroll
        for (int g = 0; g < 2; g++) {
            int nl = g * 64 + tn;
            int n  = n0 + nl;
            if (n + 4 <= N) {
                float4 v;
                v.x = acc[i][g * 4 + 0] * sInv[nl + 0];
                v.y = acc[i][g * 4 + 1] * sInv[nl + 1];
                v.z = acc[i][g * 4 + 2] * sInv[nl + 2];
                v.w = acc[i][g * 4 + 3] * sInv[nl + 3];
                *(float4*)(Crow + n) = v;
            }
        }
    }
}

// ---------------------------------------------------------------------------
// Phase 2: per test point, top-k over its sim row + majority vote.
// Block per test point (256 threads). Each thread keeps a sorted local top-k
// (threshold register makes the common path a single compare). Merge via k
// rounds of block argmax over sorted per-thread cursors.
// ---------------------------------------------------------------------------
__global__ __launch_bounds__(256)
void topk_vote_kernel(const int* __restrict__ labels,
                      const int* __restrict__ kptr,
                      float* __restrict__ out, int N)
{
    const int m   = blockIdx.x;
    const int tid = threadIdx.x;
    int k = kptr ? *kptr : 20;
    if (k < 1) k = 1;
    if (k > MAXK) k = MAXK;

    const float* row = g_sims + (size_t)m * N;

    float tv[MAXK];
    int   ti[MAXK];
    int   cnt = 0;
    float thr = -CUDART_INF_F;

    auto consider = [&](float v, int j) {
        if (cnt == k) {
            if (v <= thr) return;
            int p = k - 1;
            while (p > 0 && tv[p - 1] < v) { tv[p] = tv[p - 1]; ti[p] = ti[p - 1]; p--; }
            tv[p] = v; ti[p] = j;
            thr = tv[k - 1];
        } else {
            int p = cnt++;
            while (p > 0 && tv[p - 1] < v) { tv[p] = tv[p - 1]; ti[p] = ti[p - 1]; p--; }
            tv[p] = v; ti[p] = j;
            if (cnt == k) thr = tv[k - 1];
        }
    };

    const int nChunks = N >> 10;   // 1024 floats per chunk (256 thr x float4)
    for (int c = 0; c < nChunks; c++) {
        int base = (c << 10) + (tid << 2);
        float4 v = *(const float4*)(row + base);
        consider(v.x, base);
        consider(v.y, base + 1);
        consider(v.z, base + 2);
        consider(v.w, base + 3);
    }
    for (int j = (nChunks << 10) + tid; j < N; j += 256)
        consider(row[j], j);

    __shared__ float sval[256];
    __shared__ int   sarg[256];
    __shared__ int   sel[MAXK];

    int cur = 0;
    for (int r = 0; r < k; r++) {
        sval[tid] = (cur < cnt) ? tv[cur] : -CUDART_INF_F;
        sarg[tid] = tid;
        __syncthreads();
        #pragma unroll
        for (int s = 128; s > 0; s >>= 1) {
            if (tid < s && sval[tid + s] > sval[tid]) {
                sval[tid] = sval[tid + s];
                sarg[tid] = sarg[tid + s];
            }
            __syncthreads();
        }
        if (tid == sarg[0]) { sel[r] = ti[cur]; cur++; }
        __syncthreads();
    }

    if (tid == 0) {
        int counts[NCLASS];
        #pragma unroll
        for (int c = 0; c < NCLASS; c++) counts[c] = 0;
        for (int r = 0; r < k; r++) {
            int lab = labels[sel[r]];
            if (lab >= 0 && lab < NCLASS) counts[lab]++;
        }
        int best = 0;
        #pragma unroll
        for (int c = 1; c < NCLASS; c++)
            if (counts[c] > counts[best]) best = c;   // strict > : ties -> smallest class
        out[m] = (float)best;
    }
}

// ---------------------------------------------------------------------------
extern "C" void kernel_launch(void* const* d_in, const int* in_sizes, int n_in,
                              void* d_out, int out_size)
{
    const float* train  = (const float*)d_in[0];
    const int*   labels = (const int*)d_in[1];
    const float* x      = (const float*)d_in[2];
    const int*   kptr   = (n_in > 3) ? (const int*)d_in[3] : nullptr;

    const int Ntrain = in_sizes[1];                       // 100000
    const int D      = in_sizes[0] / (Ntrain > 0 ? Ntrain : 1);  // 256
    const int Mtest  = out_size;                          // 2048

    // Phase 0: train inverse norms (warp per row)
    {
        long long totalThreads = (long long)Ntrain * 32;
        int blocks = (int)((totalThreads + 255) / 256);
        norm_kernel<<<blocks, 256>>>(train, Ntrain, D);
    }

    // Phase 1: scaled similarity GEMM. grid.x = M tiles (fast dim -> x stays
    // in L2, each train tile DRAM-read once across all 16 m-tiles).
    {
        dim3 grid((Mtest + 127) / 128, (Ntrain + 127) / 128);
        gemm_sim_kernel<<<grid, 256>>>(x, train, Mtest, Ntrain, D);
    }

    // Phase 2: top-k + vote, one block per test point
    {
        topk_vote_kernel<<<Mtest, 256>>>(labels, kptr, (float*)d_out, Ntrain);
    }
}

// round 5
// speedup vs baseline: 1.1538x; 1.1538x over previous
#include <cuda_runtime.h>
#include <cuda_bf16.h>
#include <math_constants.h>
#include <cstdint>
#include <cstddef>

// ===========================================================================
// KNN classifier (cosine sim, top-k=20 vote over 9 classes)
//   d_in[0] train_features [100000, 256] f32
//   d_in[1] train_labels   [100000]      i32
//   d_in[2] x              [2048, 256]   f32
//   d_in[3] k              scalar i32 (device)
//   out     [2048] f32 class ids
//
// sim ordering = dot(x, t*invnorm(t)); ||x|| constant per test row -> dropped.
// bf16x2 split: v = hi + lo;  x.t ~= x_hi t_hi + x_hi t_lo + x_lo t_hi
// packed into ONE bf16 GEMM with K=768:
//   A' = [x_hi | x_hi | x_lo]   (2048 x 768)
//   B' = [t_hi | t_lo | t_hi]   (100096 x 768, rows >= N zeroed)
// GEMM: baseline-PTX tensor cores -- ldmatrix + mma.sync.m16n8k16 bf16
// (sm_80+ feature set; the bench targets sm_100 base, where tcgen05 is
// unavailable). 128x128x32 CTA tile, 8 warps x (64x32), double-buffered smem.
// ===========================================================================

#define NCLASS 9
#define MAXK   32

#define BM 128
#define BN 128
#define BK 32
#define KTOT 768
#define NCH (KTOT / BK)          // 24
#define APITCH 40                // bf16 row pitch (pad 32 -> 40, 80 bytes)

// ----- scratch (device globals: allowed no-alloc workaround) ---------------
static __device__ __align__(1024) float         g_sims[(size_t)2048 * 100000];
static __device__ __align__(1024) __nv_bfloat16 g_bp[(size_t)100096 * 768];
static __device__ __align__(1024) __nv_bfloat16 g_ap[(size_t)2048 * 768];

// ----- PTX helpers ---------------------------------------------------------
__device__ __forceinline__ uint32_t smem_u32(const void* p) {
    uint32_t a;
    asm("{ .reg .u64 t; cvta.to.shared.u64 t, %1; cvt.u32.u64 %0, t; }"
        : "=r"(a) : "l"(p));
    return a;
}

__device__ __forceinline__ void ldsm_x4(uint32_t& r0, uint32_t& r1,
                                        uint32_t& r2, uint32_t& r3, uint32_t addr) {
    asm volatile("ldmatrix.sync.aligned.m8n8.x4.shared.b16 {%0,%1,%2,%3}, [%4];"
                 : "=r"(r0), "=r"(r1), "=r"(r2), "=r"(r3) : "r"(addr));
}
__device__ __forceinline__ void ldsm_x2(uint32_t& r0, uint32_t& r1, uint32_t addr) {
    asm volatile("ldmatrix.sync.aligned.m8n8.x2.shared.b16 {%0,%1}, [%2];"
                 : "=r"(r0), "=r"(r1) : "r"(addr));
}
__device__ __forceinline__ void mma_16816(float* c, const uint32_t* a, const uint32_t* b) {
    asm volatile("mma.sync.aligned.m16n8k16.row.col.f32.bf16.bf16.f32 "
                 "{%0,%1,%2,%3}, {%4,%5,%6,%7}, {%8,%9}, {%0,%1,%2,%3};"
                 : "+f"(c[0]), "+f"(c[1]), "+f"(c[2]), "+f"(c[3])
                 : "r"(a[0]), "r"(a[1]), "r"(a[2]), "r"(a[3]), "r"(b[0]), "r"(b[1]));
}

// ===========================================================================
// Phase 0a: normalize + bf16-split + pack train rows -> B' [t_hi | t_lo | t_hi]
// ===========================================================================
__global__ void pack_train_kernel(const float* __restrict__ T, int n, int npad)
{
    int row  = blockIdx.x * 8 + (threadIdx.x >> 5);
    int lane = threadIdx.x & 31;
    if (row >= npad) return;
    __nv_bfloat16* out = g_bp + (size_t)row * KTOT;
    if (row >= n) {
        for (int i = lane; i < KTOT; i += 32) out[i] = __float2bfloat16(0.0f);
        return;
    }
    const float* r = T + (size_t)row * 256;
    float4 v0 = *(const float4*)(r + lane * 4);
    float4 v1 = *(const float4*)(r + 128 + lane * 4);
    float s = v0.x*v0.x + v0.y*v0.y + v0.z*v0.z + v0.w*v0.w
            + v1.x*v1.x + v1.y*v1.y + v1.z*v1.z + v1.w*v1.w;
    #pragma unroll
    for (int o = 16; o > 0; o >>= 1) s += __shfl_xor_sync(0xffffffffu, s, o);
    float inv = rsqrtf(fmaxf(s, 1e-30f));

    float e[8] = {v0.x, v0.y, v0.z, v0.w, v1.x, v1.y, v1.z, v1.w};
    #pragma unroll
    for (int j = 0; j < 8; j++) {
        int idx = (j < 4) ? (lane * 4 + j) : (128 + lane * 4 + j - 4);
        float v = e[j] * inv;
        __nv_bfloat16 hi = __float2bfloat16(v);
        __nv_bfloat16 lo = __float2bfloat16(v - __bfloat162float(hi));
        out[idx]       = hi;
        out[256 + idx] = lo;
        out[512 + idx] = hi;
    }
}

// Phase 0b: split + pack x rows -> A' [x_hi | x_hi | x_lo]
__global__ void pack_x_kernel(const float* __restrict__ X, int m)
{
    int row  = blockIdx.x * 8 + (threadIdx.x >> 5);
    int lane = threadIdx.x & 31;
    if (row >= m) return;
    const float* r = X + (size_t)row * 256;
    __nv_bfloat16* out = g_ap + (size_t)row * KTOT;
    float4 v0 = *(const float4*)(r + lane * 4);
    float4 v1 = *(const float4*)(r + 128 + lane * 4);
    float e[8] = {v0.x, v0.y, v0.z, v0.w, v1.x, v1.y, v1.z, v1.w};
    #pragma unroll
    for (int j = 0; j < 8; j++) {
        int idx = (j < 4) ? (lane * 4 + j) : (128 + lane * 4 + j - 4);
        float v = e[j];
        __nv_bfloat16 hi = __float2bfloat16(v);
        __nv_bfloat16 lo = __float2bfloat16(v - __bfloat162float(hi));
        out[idx]       = hi;
        out[256 + idx] = hi;
        out[512 + idx] = lo;
    }
}

// ===========================================================================
// Phase 1: HMMA bf16 GEMM, 128x128 CTA tile, BK=32, double-buffered smem.
// 256 threads = 8 warps, warp tile 64x32 (4 m-frags x 4 n-frags).
// ===========================================================================
__global__ __launch_bounds__(256)
void gemm_hmma_kernel(const __nv_bfloat16* __restrict__ Ain,
                      const __nv_bfloat16* __restrict__ Bin,
                      int Nn)
{
    __shared__ __align__(16) __nv_bfloat16 As[2][BM][APITCH];
    __shared__ __align__(16) __nv_bfloat16 Bs[2][BN][APITCH];

    const int tid  = threadIdx.x;
    const int lane = tid & 31;
    const int w    = tid >> 5;
    const int wm   = w & 1;            // 2 M slabs of 64
    const int wn   = w >> 1;           // 4 N slabs of 32
    const int m0   = blockIdx.x * BM;
    const int n0   = blockIdx.y * BN;

    // global-load mapping: idx -> row = idx>>2 (0..127), quad q = idx&3 (16B)
    const int ldRow = tid >> 2;
    const int ldQ   = (tid & 3) * 8;   // bf16 offset of the 16B quad
    const __nv_bfloat16* Aptr = Ain + (size_t)(m0 + ldRow) * KTOT + ldQ;
    const __nv_bfloat16* Aptr2 = Ain + (size_t)(m0 + 64 + ldRow) * KTOT + ldQ;
    const __nv_bfloat16* Bptr = Bin + (size_t)(n0 + ldRow) * KTOT + ldQ;
    const __nv_bfloat16* Bptr2 = Bin + (size_t)(n0 + 64 + ldRow) * KTOT + ldQ;

    float acc[4][4][4];
    #pragma unroll
    for (int i = 0; i < 4; i++)
        #pragma unroll
        for (int j = 0; j < 4; j++)
            #pragma unroll
            for (int q = 0; q < 4; q++) acc[i][j][q] = 0.f;

    // ldmatrix base addresses (per thread, stage-relative offsets added later)
    // A frag: row = mslab + mf*16 + (lane&15), colq = (lane>>4)*8
    // B frag: row = nslab + nf*8  + (lane&7),  colq = ((lane>>3)&1)*8
    const uint32_t aAddr0 = smem_u32(&As[0][wm * 64 + (lane & 15)][(lane >> 4) * 8]);
    const uint32_t bAddr0 = smem_u32(&Bs[0][wn * 32 + (lane & 7)][((lane >> 3) & 1) * 8]);
    const uint32_t stageA = (uint32_t)(BM * APITCH * 2);   // bytes per A stage
    const uint32_t stageB = (uint32_t)(BN * APITCH * 2);

    uint4 pa, pa2, pb, pb2;

    // prologue: load chunk 0
    pa  = *(const uint4*)Aptr;   pa2 = *(const uint4*)Aptr2;
    pb  = *(const uint4*)Bptr;   pb2 = *(const uint4*)Bptr2;
    *(uint4*)&As[0][ldRow][ldQ]      = pa;
    *(uint4*)&As[0][64 + ldRow][ldQ] = pa2;
    *(uint4*)&Bs[0][ldRow][ldQ]      = pb;
    *(uint4*)&Bs[0][64 + ldRow][ldQ] = pb2;
    __syncthreads();

    for (int c = 0; c < NCH; c++) {
        const int s = c & 1;
        if (c + 1 < NCH) {
            const int koff = (c + 1) * BK;
            pa  = *(const uint4*)(Aptr  + koff);
            pa2 = *(const uint4*)(Aptr2 + koff);
            pb  = *(const uint4*)(Bptr  + koff);
            pb2 = *(const uint4*)(Bptr2 + koff);
        }

        const uint32_t aAddr = aAddr0 + s * stageA;
        const uint32_t bAddr = bAddr0 + s * stageB;
        #pragma unroll
        for (int ks = 0; ks < 2; ks++) {
            const uint32_t kOffB = ks * 16 * 2;    // 16 bf16 = 32 bytes
            uint32_t a[4][4];
            #pragma unroll
            for (int mf = 0; mf < 4; mf++)
                ldsm_x4(a[mf][0], a[mf][1], a[mf][2], a[mf][3],
                        aAddr + mf * 16 * (APITCH * 2) + kOffB);
            #pragma unroll
            for (int nf = 0; nf < 4; nf++) {
                uint32_t b[2];
                ldsm_x2(b[0], b[1], bAddr + nf * 8 * (APITCH * 2) + kOffB);
                #pragma unroll
                for (int mf = 0; mf < 4; mf++)
                    mma_16816(acc[mf][nf], a[mf], b);
            }
        }

        if (c + 1 < NCH) {
            const int ns = (c + 1) & 1;
            __syncthreads();     // all warps done with stage ns's previous data
            *(uint4*)&As[ns][ldRow][ldQ]      = pa;
            *(uint4*)&As[ns][64 + ldRow][ldQ] = pa2;
            *(uint4*)&Bs[ns][ldRow][ldQ]      = pb;
            *(uint4*)&Bs[ns][64 + ldRow][ldQ] = pb2;
            __syncthreads();
        }
    }

    // ---- epilogue: direct float2 stores (4-lane groups cover 32B sectors) ----
    const int mW = m0 + wm * 64;
    const int nW = n0 + wn * 32;
    #pragma unroll
    for (int mf = 0; mf < 4; mf++) {
        const int r0 = mW + mf * 16 + (lane >> 2);
        #pragma unroll
        for (int nf = 0; nf < 4; nf++) {
            const int col = nW + nf * 8 + (lane & 3) * 2;
            if (col < Nn) {
                float2 v0 = make_float2(acc[mf][nf][0], acc[mf][nf][1]);
                float2 v1 = make_float2(acc[mf][nf][2], acc[mf][nf][3]);
                *(float2*)(g_sims + (size_t)r0 * Nn + col)       = v0;
                *(float2*)(g_sims + (size_t)(r0 + 8) * Nn + col) = v1;
            }
        }
    }
}

// ===========================================================================
// Phase 2: per test point, top-k over its sim row + majority vote.
// ===========================================================================
__global__ __launch_bounds__(256)
void topk_vote_kernel(const int* __restrict__ labels,
                      const int* __restrict__ kptr,
                      float* __restrict__ out, int N)
{
    const int m   = blockIdx.x;
    const int tid = threadIdx.x;
    int k = kptr ? *kptr : 20;
    if (k < 1) k = 1;
    if (k > MAXK) k = MAXK;

    const float* row = g_sims + (size_t)m * N;

    float tv[MAXK];
    int   ti[MAXK];
    int   cnt = 0;
    float thr = -CUDART_INF_F;

    auto consider = [&](float v, int j) {
        if (cnt == k) {
            if (v <= thr) return;
            int p = k - 1;
            while (p > 0 && tv[p - 1] < v) { tv[p] = tv[p - 1]; ti[p] = ti[p - 1]; p--; }
            tv[p] = v; ti[p] = j;
            thr = tv[k - 1];
        } else {
            int p = cnt++;
            while (p > 0 && tv[p - 1] < v) { tv[p] = tv[p - 1]; ti[p] = ti[p - 1]; p--; }
            tv[p] = v; ti[p] = j;
            if (cnt == k) thr = tv[k - 1];
        }
    };

    const int nChunks = N >> 10;
    for (int c = 0; c < nChunks; c++) {
        int bse = (c << 10) + (tid << 2);
        float4 v = *(const float4*)(row + bse);
        consider(v.x, bse);
        consider(v.y, bse + 1);
        consider(v.z, bse + 2);
        consider(v.w, bse + 3);
    }
    for (int j = (nChunks << 10) + tid; j < N; j += 256)
        consider(row[j], j);

    __shared__ float sval[256];
    __shared__ int   sarg[256];
    __shared__ int   sel[MAXK];

    int cur = 0;
    for (int r = 0; r < k; r++) {
        sval[tid] = (cur < cnt) ? tv[cur] : -CUDART_INF_F;
        sarg[tid] = tid;
        __syncthreads();
        #pragma unroll
        for (int s = 128; s > 0; s >>= 1) {
            if (tid < s && sval[tid + s] > sval[tid]) {
                sval[tid] = sval[tid + s];
                sarg[tid] = sarg[tid + s];
            }
            __syncthreads();
        }
        if (tid == sarg[0]) { sel[r] = ti[cur]; cur++; }
        __syncthreads();
    }

    if (tid == 0) {
        int counts[NCLASS];
        #pragma unroll
        for (int c = 0; c < NCLASS; c++) counts[c] = 0;
        for (int r = 0; r < k; r++) {
            int lab = labels[sel[r]];
            if (lab >= 0 && lab < NCLASS) counts[lab]++;
        }
        int best = 0;
        #pragma unroll
        for (int c = 1; c < NCLASS; c++)
            if (counts[c] > counts[best]) best = c;   // ties -> smallest class
        out[m] = (float)best;
    }
}

// ===========================================================================
// host launcher
// ===========================================================================
extern "C" void kernel_launch(void* const* d_in, const int* in_sizes, int n_in,
                              void* d_out, int out_size)
{
    const float* train  = (const float*)d_in[0];
    const int*   labels = (const int*)d_in[1];
    const float* x      = (const float*)d_in[2];
    const int*   kptr   = (n_in > 3) ? (const int*)d_in[3] : nullptr;

    const int Ntrain = in_sizes[1];                               // 100000
    const int Mtest  = out_size;                                  // 2048
    const int NPAD   = ((Ntrain + BN - 1) / BN) * BN;             // 100096

    void *apPtr = nullptr, *bpPtr = nullptr;
    cudaGetSymbolAddress(&apPtr, g_ap);
    cudaGetSymbolAddress(&bpPtr, g_bp);

    // Phase 0: pack/split (warp per row)
    pack_train_kernel<<<(NPAD + 7) / 8, 256>>>(train, Ntrain, NPAD);
    pack_x_kernel<<<(Mtest + 7) / 8, 256>>>(x, Mtest);

    // Phase 1: HMMA GEMM. grid.x = m-tiles (fast dim) so CTAs sharing one
    // B tile run together -> B tile L2-resident, DRAM-read once.
    {
        dim3 grid(Mtest / BM, NPAD / BN);
        gemm_hmma_kernel<<<grid, 256>>>(
            (const __nv_bfloat16*)apPtr, (const __nv_bfloat16*)bpPtr, Ntrain);
    }

    // Phase 2: top-k + vote, one block per test point
    topk_vote_kernel<<<Mtest, 256>>>(labels, kptr, (float*)d_out, Ntrain);
}

// round 6
// speedup vs baseline: 5.1765x; 4.4863x over previous
#include <cuda_runtime.h>
#include <cuda_bf16.h>
#include <math_constants.h>
#include <cstdint>
#include <cstddef>

// ===========================================================================
// KNN classifier (cosine sim, top-k=20 vote over 9 classes)
//   d_in[0] train_features [100000, 256] f32
//   d_in[1] train_labels   [100000]      i32
//   d_in[2] x              [2048, 256]   f32
//   d_in[3] k              scalar i32 (device)
//   out     [2048] f32 class ids
//
// sim ordering = dot(x, t*invnorm(t)); ||x|| constant per test row -> dropped.
// bf16x2 split: v = hi + lo;  x.t ~= x_hi t_hi + x_hi t_lo + x_lo t_hi
// packed into ONE bf16 GEMM with K=768:
//   A' = [x_hi | x_hi | x_lo]   (2048 x 768)
//   B' = [t_hi | t_lo | t_hi]   (100096 x 768, rows >= N zeroed)
// GEMM: ldmatrix + mma.sync.m16n8k16 bf16 (sm_100 base target: no tcgen05).
// Top-k: threshold-filter (k-th largest of per-thread maxima) + smem
// compaction + warp-0 argmax selection. Exact; slow fallback on overflow.
// ===========================================================================

#define NCLASS 9
#define MAXK   32

#define BM 128
#define BN 128
#define BK 32
#define KTOT 768
#define NCH (KTOT / BK)          // 24
#define APITCH 40                // bf16 row pitch (pad 32 -> 40, 80 bytes)
#define CAP 2048                 // candidate buffer (u64) per block

// ----- scratch (device globals: allowed no-alloc workaround) ---------------
static __device__ __align__(1024) float         g_sims[(size_t)2048 * 100000];
static __device__ __align__(1024) __nv_bfloat16 g_bp[(size_t)100096 * 768];
static __device__ __align__(1024) __nv_bfloat16 g_ap[(size_t)2048 * 768];

// ----- PTX helpers ---------------------------------------------------------
__device__ __forceinline__ uint32_t smem_u32(const void* p) {
    uint32_t a;
    asm("{ .reg .u64 t; cvta.to.shared.u64 t, %1; cvt.u32.u64 %0, t; }"
        : "=r"(a) : "l"(p));
    return a;
}

__device__ __forceinline__ void ldsm_x4(uint32_t& r0, uint32_t& r1,
                                        uint32_t& r2, uint32_t& r3, uint32_t addr) {
    asm volatile("ldmatrix.sync.aligned.m8n8.x4.shared.b16 {%0,%1,%2,%3}, [%4];"
                 : "=r"(r0), "=r"(r1), "=r"(r2), "=r"(r3) : "r"(addr));
}
__device__ __forceinline__ void ldsm_x2(uint32_t& r0, uint32_t& r1, uint32_t addr) {
    asm volatile("ldmatrix.sync.aligned.m8n8.x2.shared.b16 {%0,%1}, [%2];"
                 : "=r"(r0), "=r"(r1) : "r"(addr));
}
__device__ __forceinline__ void mma_16816(float* c, const uint32_t* a, const uint32_t* b) {
    asm volatile("mma.sync.aligned.m16n8k16.row.col.f32.bf16.bf16.f32 "
                 "{%0,%1,%2,%3}, {%4,%5,%6,%7}, {%8,%9}, {%0,%1,%2,%3};"
                 : "+f"(c[0]), "+f"(c[1]), "+f"(c[2]), "+f"(c[3])
                 : "r"(a[0]), "r"(a[1]), "r"(a[2]), "r"(a[3]), "r"(b[0]), "r"(b[1]));
}

// monotonic f32 -> u32 key (order-preserving incl. negatives)
__device__ __forceinline__ uint32_t fkey(float v) {
    uint32_t b = __float_as_uint(v);
    return (b & 0x80000000u) ? ~b : (b | 0x80000000u);
}

// ===========================================================================
// Phase 0a: normalize + bf16-split + pack train rows -> B' [t_hi | t_lo | t_hi]
// ===========================================================================
__global__ void pack_train_kernel(const float* __restrict__ T, int n, int npad)
{
    int row  = blockIdx.x * 8 + (threadIdx.x >> 5);
    int lane = threadIdx.x & 31;
    if (row >= npad) return;
    __nv_bfloat16* out = g_bp + (size_t)row * KTOT;
    if (row >= n) {
        for (int i = lane; i < KTOT; i += 32) out[i] = __float2bfloat16(0.0f);
        return;
    }
    const float* r = T + (size_t)row * 256;
    float4 v0 = *(const float4*)(r + lane * 4);
    float4 v1 = *(const float4*)(r + 128 + lane * 4);
    float s = v0.x*v0.x + v0.y*v0.y + v0.z*v0.z + v0.w*v0.w
            + v1.x*v1.x + v1.y*v1.y + v1.z*v1.z + v1.w*v1.w;
    #pragma unroll
    for (int o = 16; o > 0; o >>= 1) s += __shfl_xor_sync(0xffffffffu, s, o);
    float inv = rsqrtf(fmaxf(s, 1e-30f));

    float e[8] = {v0.x, v0.y, v0.z, v0.w, v1.x, v1.y, v1.z, v1.w};
    #pragma unroll
    for (int j = 0; j < 8; j++) {
        int idx = (j < 4) ? (lane * 4 + j) : (128 + lane * 4 + j - 4);
        float v = e[j] * inv;
        __nv_bfloat16 hi = __float2bfloat16(v);
        __nv_bfloat16 lo = __float2bfloat16(v - __bfloat162float(hi));
        out[idx]       = hi;
        out[256 + idx] = lo;
        out[512 + idx] = hi;
    }
}

// Phase 0b: split + pack x rows -> A' [x_hi | x_hi | x_lo]
__global__ void pack_x_kernel(const float* __restrict__ X, int m)
{
    int row  = blockIdx.x * 8 + (threadIdx.x >> 5);
    int lane = threadIdx.x & 31;
    if (row >= m) return;
    const float* r = X + (size_t)row * 256;
    __nv_bfloat16* out = g_ap + (size_t)row * KTOT;
    float4 v0 = *(const float4*)(r + lane * 4);
    float4 v1 = *(const float4*)(r + 128 + lane * 4);
    float e[8] = {v0.x, v0.y, v0.z, v0.w, v1.x, v1.y, v1.z, v1.w};
    #pragma unroll
    for (int j = 0; j < 8; j++) {
        int idx = (j < 4) ? (lane * 4 + j) : (128 + lane * 4 + j - 4);
        float v = e[j];
        __nv_bfloat16 hi = __float2bfloat16(v);
        __nv_bfloat16 lo = __float2bfloat16(v - __bfloat162float(hi));
        out[idx]       = hi;
        out[256 + idx] = hi;
        out[512 + idx] = lo;
    }
}

// ===========================================================================
// Phase 1: HMMA bf16 GEMM, 128x128 CTA tile, BK=32, double-buffered smem.
// (unchanged from R5 -- passed with rel_err 0)
// ===========================================================================
__global__ __launch_bounds__(256)
void gemm_hmma_kernel(const __nv_bfloat16* __restrict__ Ain,
                      const __nv_bfloat16* __restrict__ Bin,
                      int Nn)
{
    __shared__ __align__(16) __nv_bfloat16 As[2][BM][APITCH];
    __shared__ __align__(16) __nv_bfloat16 Bs[2][BN][APITCH];

    const int tid  = threadIdx.x;
    const int lane = tid & 31;
    const int w    = tid >> 5;
    const int wm   = w & 1;
    const int wn   = w >> 1;
    const int m0   = blockIdx.x * BM;
    const int n0   = blockIdx.y * BN;

    const int ldRow = tid >> 2;
    const int ldQ   = (tid & 3) * 8;
    const __nv_bfloat16* Aptr  = Ain + (size_t)(m0 + ldRow) * KTOT + ldQ;
    const __nv_bfloat16* Aptr2 = Ain + (size_t)(m0 + 64 + ldRow) * KTOT + ldQ;
    const __nv_bfloat16* Bptr  = Bin + (size_t)(n0 + ldRow) * KTOT + ldQ;
    const __nv_bfloat16* Bptr2 = Bin + (size_t)(n0 + 64 + ldRow) * KTOT + ldQ;

    float acc[4][4][4];
    #pragma unroll
    for (int i = 0; i < 4; i++)
        #pragma unroll
        for (int j = 0; j < 4; j++)
            #pragma unroll
            for (int q = 0; q < 4; q++) acc[i][j][q] = 0.f;

    const uint32_t aAddr0 = smem_u32(&As[0][wm * 64 + (lane & 15)][(lane >> 4) * 8]);
    const uint32_t bAddr0 = smem_u32(&Bs[0][wn * 32 + (lane & 7)][((lane >> 3) & 1) * 8]);
    const uint32_t stageA = (uint32_t)(BM * APITCH * 2);
    const uint32_t stageB = (uint32_t)(BN * APITCH * 2);

    uint4 pa, pa2, pb, pb2;

    pa  = *(const uint4*)Aptr;   pa2 = *(const uint4*)Aptr2;
    pb  = *(const uint4*)Bptr;   pb2 = *(const uint4*)Bptr2;
    *(uint4*)&As[0][ldRow][ldQ]      = pa;
    *(uint4*)&As[0][64 + ldRow][ldQ] = pa2;
    *(uint4*)&Bs[0][ldRow][ldQ]      = pb;
    *(uint4*)&Bs[0][64 + ldRow][ldQ] = pb2;
    __syncthreads();

    for (int c = 0; c < NCH; c++) {
        const int s = c & 1;
        if (c + 1 < NCH) {
            const int koff = (c + 1) * BK;
            pa  = *(const uint4*)(Aptr  + koff);
            pa2 = *(const uint4*)(Aptr2 + koff);
            pb  = *(const uint4*)(Bptr  + koff);
            pb2 = *(const uint4*)(Bptr2 + koff);
        }

        const uint32_t aAddr = aAddr0 + s * stageA;
        const uint32_t bAddr = bAddr0 + s * stageB;
        #pragma unroll
        for (int ks = 0; ks < 2; ks++) {
            const uint32_t kOffB = ks * 16 * 2;
            uint32_t a[4][4];
            #pragma unroll
            for (int mf = 0; mf < 4; mf++)
                ldsm_x4(a[mf][0], a[mf][1], a[mf][2], a[mf][3],
                        aAddr + mf * 16 * (APITCH * 2) + kOffB);
            #pragma unroll
            for (int nf = 0; nf < 4; nf++) {
                uint32_t b[2];
                ldsm_x2(b[0], b[1], bAddr + nf * 8 * (APITCH * 2) + kOffB);
                #pragma unroll
                for (int mf = 0; mf < 4; mf++)
                    mma_16816(acc[mf][nf], a[mf], b);
            }
        }

        if (c + 1 < NCH) {
            const int ns = (c + 1) & 1;
            __syncthreads();
            *(uint4*)&As[ns][ldRow][ldQ]      = pa;
            *(uint4*)&As[ns][64 + ldRow][ldQ] = pa2;
            *(uint4*)&Bs[ns][ldRow][ldQ]      = pb;
            *(uint4*)&Bs[ns][64 + ldRow][ldQ] = pb2;
            __syncthreads();
        }
    }

    const int mW = m0 + wm * 64;
    const int nW = n0 + wn * 32;
    #pragma unroll
    for (int mf = 0; mf < 4; mf++) {
        const int r0 = mW + mf * 16 + (lane >> 2);
        #pragma unroll
        for (int nf = 0; nf < 4; nf++) {
            const int col = nW + nf * 8 + (lane & 3) * 2;
            if (col < Nn) {
                float2 v0 = make_float2(acc[mf][nf][0], acc[mf][nf][1]);
                float2 v1 = make_float2(acc[mf][nf][2], acc[mf][nf][3]);
                *(float2*)(g_sims + (size_t)r0 * Nn + col)       = v0;
                *(float2*)(g_sims + (size_t)(r0 + 8) * Nn + col) = v1;
            }
        }
    }
}

// ===========================================================================
// Phase 2 (NEW): threshold-filter top-k + vote.
// Pass 1: per-thread max -> warp0 extracts k-th largest of 256 maxima = theta.
//         (<= true k-th value of the row, so filter keeps a superset)
// Pass 2: compact v >= theta into smem as u64 keys (value desc, index asc).
// Warp0: k rounds of shfl argmax; lane0 votes. Exact fallback on overflow.
// ===========================================================================
__global__ __launch_bounds__(256)
void topk_vote_kernel(const int* __restrict__ labels,
                      const int* __restrict__ kptr,
                      float* __restrict__ out, int N)
{
    const int m    = blockIdx.x;
    const int tid  = threadIdx.x;
    const int lane = tid & 31;
    const int warp = tid >> 5;
    int k = kptr ? *kptr : 20;
    if (k < 1) k = 1;
    if (k > MAXK) k = MAXK;

    const float* row = g_sims + (size_t)m * N;

    __shared__ float smax[256];
    __shared__ unsigned long long cand[CAP];
    __shared__ int   scnt;
    __shared__ float sth;
    __shared__ unsigned long long ssel[MAXK];

    // ---- pass 1: per-thread max (branch-free streaming) ----
    float mx = -CUDART_INF_F;
    const int nChunks = N >> 10;
    for (int c = 0; c < nChunks; c++) {
        int base = (c << 10) + (tid << 2);
        float4 v = *(const float4*)(row + base);
        mx = fmaxf(mx, fmaxf(fmaxf(v.x, v.y), fmaxf(v.z, v.w)));
    }
    for (int j = (nChunks << 10) + tid; j < N; j += 256)
        mx = fmaxf(mx, row[j]);
    smax[tid] = mx;
    if (tid == 0) scnt = 0;
    __syncthreads();

    // ---- warp0: k-th largest of the 256 thread maxima -> theta ----
    if (warp == 0) {
        float th = -CUDART_INF_F;
        for (int r = 0; r < k; r++) {
            float lv = -CUDART_INF_F; int la = -1;
            #pragma unroll
            for (int s = 0; s < 8; s++) {
                float v = smax[lane + s * 32];
                if (v > lv) { lv = v; la = lane + s * 32; }
            }
            #pragma unroll
            for (int o = 16; o > 0; o >>= 1) {
                float ov = __shfl_down_sync(0xffffffffu, lv, o);
                int   oa = __shfl_down_sync(0xffffffffu, la, o);
                if (ov > lv) { lv = ov; la = oa; }
            }
            la = __shfl_sync(0xffffffffu, la, 0);
            th = __shfl_sync(0xffffffffu, lv, 0);
            if (lane == 0 && la >= 0) smax[la] = -CUDART_INF_F;
        }
        if (lane == 0) sth = th;
    }
    __syncthreads();
    const float th = sth;

    // ---- pass 2: compact candidates >= theta ----
    for (int c = 0; c < nChunks; c++) {
        int base = (c << 10) + (tid << 2);
        float4 v = *(const float4*)(row + base);
        #pragma unroll
        for (int q = 0; q < 4; q++) {
            float vv = (q == 0) ? v.x : (q == 1) ? v.y : (q == 2) ? v.z : v.w;
            if (vv >= th) {
                int p = atomicAdd(&scnt, 1);
                if (p < CAP)
                    cand[p] = ((unsigned long long)fkey(vv) << 32) |
                              (uint32_t)(~(uint32_t)(base + q));
            }
        }
    }
    for (int j = (nChunks << 10) + tid; j < N; j += 256) {
        float vv = row[j];
        if (vv >= th) {
            int p = atomicAdd(&scnt, 1);
            if (p < CAP)
                cand[p] = ((unsigned long long)fkey(vv) << 32) |
                          (uint32_t)(~(uint32_t)j);
        }
    }
    __syncthreads();
    const int cnt = scnt;

    if (cnt <= CAP) {
        // ---- warp0: k rounds of argmax over candidates ----
        if (warp == 0) {
            for (int r = 0; r < k; r++) {
                unsigned long long lv = 0ull; int la = -1;
                for (int s = lane; s < cnt; s += 32) {
                    unsigned long long c2 = cand[s];
                    if (c2 > lv) { lv = c2; la = s; }
                }
                #pragma unroll
                for (int o = 16; o > 0; o >>= 1) {
                    unsigned long long ov = __shfl_down_sync(0xffffffffu, lv, o);
                    int oa = __shfl_down_sync(0xffffffffu, la, o);
                    if (ov > lv) { lv = ov; la = oa; }
                }
                la = __shfl_sync(0xffffffffu, la, 0);
                lv = __shfl_sync(0xffffffffu, lv, 0);
                if (lane == 0) {
                    ssel[r] = lv;
                    if (la >= 0) cand[la] = 0ull;   // disable winner
                }
                __syncwarp();
            }
            if (lane == 0) {
                int counts[NCLASS];
                #pragma unroll
                for (int c = 0; c < NCLASS; c++) counts[c] = 0;
                for (int r = 0; r < k; r++) {
                    if (ssel[r] == 0ull) continue;
                    int j = (int)(~(uint32_t)(ssel[r] & 0xFFFFFFFFull));
                    int lab = labels[j];
                    if (lab >= 0 && lab < NCLASS) counts[lab]++;
                }
                int best = 0;
                #pragma unroll
                for (int c = 1; c < NCLASS; c++)
                    if (counts[c] > counts[best]) best = c;  // ties -> smallest
                out[m] = (float)best;
            }
        }
        return;
    }

    // ---- exact fallback (overflow; never hit on this data) ----
    {
        float tv[MAXK]; int ti[MAXK];
        int cnt2 = 0; float thr = -CUDART_INF_F;
        auto consider = [&](float v, int j) {
            if (cnt2 == k) {
                if (v <= thr) return;
                int p = k - 1;
                while (p > 0 && tv[p-1] < v) { tv[p]=tv[p-1]; ti[p]=ti[p-1]; p--; }
                tv[p] = v; ti[p] = j; thr = tv[k-1];
            } else {
                int p = cnt2++;
                while (p > 0 && tv[p-1] < v) { tv[p]=tv[p-1]; ti[p]=ti[p-1]; p--; }
                tv[p] = v; ti[p] = j;
                if (cnt2 == k) thr = tv[k-1];
            }
        };
        for (int c = 0; c < nChunks; c++) {
            int base = (c << 10) + (tid << 2);
            float4 v = *(const float4*)(row + base);
            consider(v.x, base); consider(v.y, base+1);
            consider(v.z, base+2); consider(v.w, base+3);
        }
        for (int j = (nChunks << 10) + tid; j < N; j += 256)
            consider(row[j], j);

        __shared__ float sval[256];
        __shared__ int   sarg[256];
        __shared__ int   selIdx[MAXK];
        int cur = 0;
        for (int r = 0; r < k; r++) {
            sval[tid] = (cur < cnt2) ? tv[cur] : -CUDART_INF_F;
            sarg[tid] = tid;
            __syncthreads();
            #pragma unroll
            for (int s = 128; s > 0; s >>= 1) {
                if (tid < s && sval[tid+s] > sval[tid]) {
                    sval[tid] = sval[tid+s]; sarg[tid] = sarg[tid+s];
                }
                __syncthreads();
            }
            if (tid == sarg[0]) { selIdx[r] = ti[cur]; cur++; }
            __syncthreads();
        }
        if (tid == 0) {
            int counts[NCLASS];
            #pragma unroll
            for (int c = 0; c < NCLASS; c++) counts[c] = 0;
            for (int r = 0; r < k; r++) {
                int lab = labels[selIdx[r]];
                if (lab >= 0 && lab < NCLASS) counts[lab]++;
            }
            int best = 0;
            #pragma unroll
            for (int c = 1; c < NCLASS; c++)
                if (counts[c] > counts[best]) best = c;
            out[m] = (float)best;
        }
    }
}

// ===========================================================================
// host launcher
// ===========================================================================
extern "C" void kernel_launch(void* const* d_in, const int* in_sizes, int n_in,
                              void* d_out, int out_size)
{
    const float* train  = (const float*)d_in[0];
    const int*   labels = (const int*)d_in[1];
    const float* x      = (const float*)d_in[2];
    const int*   kptr   = (n_in > 3) ? (const int*)d_in[3] : nullptr;

    const int Ntrain = in_sizes[1];                               // 100000
    const int Mtest  = out_size;                                  // 2048
    const int NPAD   = ((Ntrain + BN - 1) / BN) * BN;             // 100096

    void *apPtr = nullptr, *bpPtr = nullptr;
    cudaGetSymbolAddress(&apPtr, g_ap);
    cudaGetSymbolAddress(&bpPtr, g_bp);

    // Phase 0: pack/split (warp per row)
    pack_train_kernel<<<(NPAD + 7) / 8, 256>>>(train, Ntrain, NPAD);
    pack_x_kernel<<<(Mtest + 7) / 8, 256>>>(x, Mtest);

    // Phase 1: HMMA GEMM. grid.x = m-tiles (fast dim) -> B tile L2-resident.
    {
        dim3 grid(Mtest / BM, NPAD / BN);
        gemm_hmma_kernel<<<grid, 256>>>(
            (const __nv_bfloat16*)apPtr, (const __nv_bfloat16*)bpPtr, Ntrain);
    }

    // Phase 2: top-k + vote, one block per test point
    topk_vote_kernel<<<Mtest, 256>>>(labels, kptr, (float*)d_out, Ntrain);
}